// round 11
// baseline (speedup 1.0000x reference)
#include <cuda_runtime.h>
#include <cstdint>

// B=4,H=8,N=2048,D=64 fp32.  out = softmax(l * softmax(2l)) @ V,  l = qk^T*scale
#define BH   32
#define SEQ  2048
#define HD   64
#define QT   128          // q rows per CTA
#define KT   128          // keys per tile
#define NK   (SEQ / KT)   // 16

#define QS 68             // Q smem stride (floats): rows 16B-aligned (272B)
#define KS 66             // K smem stride: rows 8B-aligned, conflict-free LDS.64
#define VS 68             // V smem stride: 16B-aligned rows
#define PS 132            // P smem stride: 16B-aligned rows

// Scratch: logits (512MB), stored k-BLOCKED within each 128-tile:
//   L[bh][q][kt*128 + pos],  pos = tx*8 + j  <->  k = kt*128 + tx + 16*j
__device__ float g_L[(size_t)BH * SEQ * SEQ];
__device__ float g_sum1[BH * SEQ];

// ---- packed f32x2 helpers (Blackwell family-wide; NOT an sm_103a-only feature) ----
__device__ __forceinline__ void fma2(uint64_t& acc, uint64_t a, uint64_t b) {
    asm("fma.rn.f32x2 %0, %1, %2, %0;" : "+l"(acc) : "l"(a), "l"(b));
}
__device__ __forceinline__ uint64_t pack2(float lo, float hi) {
    uint64_t r; asm("mov.b64 %0, {%1, %2};" : "=l"(r) : "f"(lo), "f"(hi)); return r;
}
__device__ __forceinline__ float2 unpack2(uint64_t v) {
    float2 f; asm("mov.b64 {%0, %1}, %2;" : "=f"(f.x), "=f"(f.y) : "l"(v)); return f;
}

// ---------------------------------------------------------------------------
// Kernel 1: L = (Q K^T)*scale (blocked layout); sum1[q] = sum_k exp(2*l)
// 256 thr: tx=tid&15, ty=tid>>4. Thread owns q rows ty+16i (i<8), k cols tx+16j (j<8).
// acc[i][j] is an f32x2 pair of PARTIAL sums over (even d, odd d) — operands are
// natural LDS.64 d-pairs, so the hot loop is pure LDS.64 + FFMA2.
// ---------------------------------------------------------------------------
__global__ void __launch_bounds__(256, 1) qk_kernel(
    const float* __restrict__ q, const float* __restrict__ k,
    const float* __restrict__ scale_p)
{
    extern __shared__ float sm[];
    float* Qs = sm;              // QT * QS
    float* Ks = sm + QT * QS;    // KT * KS

    const float scale = *scale_p;
    const int tid = threadIdx.x, tx = tid & 15, ty = tid >> 4;
    const int bh = blockIdx.y, q0 = blockIdx.x * QT;

    // Load Q tile (128x64): 2048 float4 / 256 thr = 8 each. Rows 16B-aligned.
    {
        const float4* qg = reinterpret_cast<const float4*>(
            q + ((size_t)bh * SEQ + q0) * HD);
        #pragma unroll
        for (int m = 0; m < 8; m++) {
            int idx = tid + 256 * m;
            int r = idx >> 4, c4 = idx & 15;
            *reinterpret_cast<float4*>(Qs + r * QS + c4 * 4) = qg[idx];
        }
    }

    float sum1p[8];
    #pragma unroll
    for (int i = 0; i < 8; i++) sum1p[i] = 0.f;

    const float4* kg = reinterpret_cast<const float4*>(k + (size_t)bh * SEQ * HD);
    float* Lb = g_L + (size_t)bh * SEQ * SEQ;

    for (int kt = 0; kt < NK; kt++) {
        __syncthreads();                       // prior tile's readers done
        // Load K tile (128x64), stride 66 -> two 8B stores per float4
        #pragma unroll
        for (int m = 0; m < 8; m++) {
            int idx = tid + 256 * m;
            int r = idx >> 4, c4 = idx & 15;
            float4 v = kg[(size_t)kt * KT * (HD / 4) + idx];
            float* d = Ks + r * KS + c4 * 4;   // (66r+4c)*4 is 8B aligned
            *reinterpret_cast<float2*>(d)     = make_float2(v.x, v.y);
            *reinterpret_cast<float2*>(d + 2) = make_float2(v.z, v.w);
        }
        __syncthreads();

        uint64_t acc[8][8];
        #pragma unroll
        for (int i = 0; i < 8; i++)
            #pragma unroll
            for (int j = 0; j < 8; j++) acc[i][j] = 0ull;

        #pragma unroll 4
        for (int d = 0; d < HD; d += 2) {
            uint64_t q2[8], k2[8];
            #pragma unroll
            for (int i = 0; i < 8; i++)        // broadcast (2 addrs/warp)
                q2[i] = *reinterpret_cast<const uint64_t*>(Qs + (ty + 16 * i) * QS + d);
            #pragma unroll
            for (int j = 0; j < 8; j++)        // 16 distinct 8B addrs, conflict-free
                k2[j] = *reinterpret_cast<const uint64_t*>(Ks + (tx + 16 * j) * KS + d);
            #pragma unroll
            for (int i = 0; i < 8; i++)
                #pragma unroll
                for (int j = 0; j < 8; j++)
                    fma2(acc[i][j], q2[i], k2[j]);
        }

        // Epilogue: horizontal add, scale, exp-accumulate, blocked coalesced store
        #pragma unroll
        for (int i = 0; i < 8; i++) {
            int r = ty + 16 * i;
            float o[8];
            #pragma unroll
            for (int j = 0; j < 8; j++) {
                float2 p = unpack2(acc[i][j]);
                float l = (p.x + p.y) * scale;
                sum1p[i] += __expf(2.f * l);
                o[j] = l;                      // value for k = tx + 16*j -> pos tx*8+j
            }
            float* dst = Lb + (size_t)(q0 + r) * SEQ + kt * KT + tx * 8;
            *reinterpret_cast<float4*>(dst)     = make_float4(o[0], o[1], o[2], o[3]);
            *reinterpret_cast<float4*>(dst + 4) = make_float4(o[4], o[5], o[6], o[7]);
        }
    }

    // Reduce sum1 over the 16 tx-lanes (groups = lanes 0-15 / 16-31; xor<=8 stays inside)
    #pragma unroll
    for (int m = 8; m >= 1; m >>= 1)
        #pragma unroll
        for (int i = 0; i < 8; i++)
            sum1p[i] += __shfl_xor_sync(0xffffffffu, sum1p[i], m);
    if (tx == 0) {
        #pragma unroll
        for (int i = 0; i < 8; i++)
            g_sum1[bh * SEQ + q0 + ty + 16 * i] = sum1p[i];
    }
}

// ---------------------------------------------------------------------------
// Kernel 2: p = exp(l * exp(2l)/sum1); out = (P V) / sum(p)
// 256 thr. P-compute: thread pr=tid>>1 handles row pr, positions ph..ph+63.
// GEMM: thread (tx,ty) owns q rows ty+16i, d cols 4tx..4tx+3 (two f32x2 pairs).
// kk iterated in blocked-pos order (sum order is free); V row = (pos&7)*16+(pos>>3).
// ---------------------------------------------------------------------------
__global__ void __launch_bounds__(256, 2) pv_kernel(
    const float* __restrict__ v, float* __restrict__ out)
{
    extern __shared__ float sm[];
    float* Ps  = sm;                         // QT * PS
    float* Vs  = sm + QT * PS;               // KT * VS
    float* s2s = Vs + KT * VS;               // QT

    const int tid = threadIdx.x, tx = tid & 15, ty = tid >> 4;
    const int bh = blockIdx.y, q0 = blockIdx.x * QT;
    const int pr = tid >> 1;                 // P-compute row
    const int ph = (tid & 1) * 64;           // position half

    const float inv1 = 1.f / g_sum1[bh * SEQ + q0 + pr];
    float sum2 = 0.f;

    uint64_t acc[8][2];
    #pragma unroll
    for (int i = 0; i < 8; i++) { acc[i][0] = 0ull; acc[i][1] = 0ull; }

    const float4* vg = reinterpret_cast<const float4*>(v + (size_t)bh * SEQ * HD);
    const float* Lrow = g_L + (size_t)bh * SEQ * SEQ + (size_t)(q0 + pr) * SEQ;

    for (int kt = 0; kt < NK; kt++) {
        __syncthreads();                     // prior tile's Ps/Vs readers done
        // Load V tile (128x64): 8 float4 each, 16B-aligned rows
        #pragma unroll
        for (int m = 0; m < 8; m++) {
            int idx = tid + 256 * m;
            int r = idx >> 4, c4 = idx & 15;
            *reinterpret_cast<float4*>(Vs + r * VS + c4 * 4) =
                vg[(size_t)kt * KT * (HD / 4) + idx];
        }
        // P-compute: 64 contiguous blocked positions per thread
        {
            const float4* Lp = reinterpret_cast<const float4*>(Lrow + kt * KT + ph);
            float* Pd = Ps + pr * PS + ph;
            #pragma unroll 4
            for (int t = 0; t < 16; t++) {
                float4 l4 = Lp[t];
                float pv4[4];
                float lv[4] = {l4.x, l4.y, l4.z, l4.w};
                #pragma unroll
                for (int e = 0; e < 4; e++) {
                    float msk = __expf(2.f * lv[e]) * inv1;
                    float p = __expf(lv[e] * msk);
                    sum2 += p;
                    pv4[e] = p;
                }
                *reinterpret_cast<float4*>(Pd + 4 * t) =
                    make_float4(pv4[0], pv4[1], pv4[2], pv4[3]);
            }
        }
        __syncthreads();

        // GEMM over 64 pos-pairs
        #pragma unroll 2
        for (int c2 = 0; c2 < 64; c2++) {
            int pos = 2 * c2;
            int t = pos >> 3, c = pos & 7;
            int k0 = c * 16 + t;             // V row for pos   (c even)
            int k1 = k0 + 16;                // V row for pos+1
            float4 v0 = *reinterpret_cast<const float4*>(Vs + k0 * VS + 4 * tx);
            float4 v1 = *reinterpret_cast<const float4*>(Vs + k1 * VS + 4 * tx);
            uint64_t v0a = pack2(v0.x, v0.y), v0b = pack2(v0.z, v0.w);
            uint64_t v1a = pack2(v1.x, v1.y), v1b = pack2(v1.z, v1.w);
            #pragma unroll
            for (int i = 0; i < 8; i++) {
                float2 pp = unpack2(*reinterpret_cast<const uint64_t*>(
                    Ps + (ty + 16 * i) * PS + pos));
                uint64_t pa = pack2(pp.x, pp.x);
                uint64_t pb = pack2(pp.y, pp.y);
                fma2(acc[i][0], pa, v0a);
                fma2(acc[i][1], pa, v0b);
                fma2(acc[i][0], pb, v1a);
                fma2(acc[i][1], pb, v1b);
            }
        }
    }

    // sum2: combine the two half-threads of each row, publish, then normalize+store
    sum2 += __shfl_xor_sync(0xffffffffu, sum2, 1);
    if ((tid & 1) == 0) s2s[pr] = sum2;
    __syncthreads();

    #pragma unroll
    for (int i = 0; i < 8; i++) {
        int r = ty + 16 * i;
        float inv2 = 1.f / s2s[r];
        float2 a = unpack2(acc[i][0]);
        float2 b = unpack2(acc[i][1]);
        float4 o = make_float4(a.x * inv2, a.y * inv2, b.x * inv2, b.y * inv2);
        *reinterpret_cast<float4*>(
            out + ((size_t)bh * SEQ + q0 + r) * HD + 4 * tx) = o;
    }
}

// ---------------------------------------------------------------------------
extern "C" void kernel_launch(void* const* d_in, const int* in_sizes, int n_in,
                              void* d_out, int out_size)
{
    const float* q     = (const float*)d_in[0];
    const float* k     = (const float*)d_in[1];
    const float* v     = (const float*)d_in[2];
    const float* scale = (const float*)d_in[3];
    float* out = (float*)d_out;

    const int smem1 = (QT * QS + KT * KS) * (int)sizeof(float);            // 68608
    const int smem2 = (QT * PS + KT * VS + QT) * (int)sizeof(float);       // 102912
    cudaFuncSetAttribute(qk_kernel, cudaFuncAttributeMaxDynamicSharedMemorySize, smem1);
    cudaFuncSetAttribute(pv_kernel, cudaFuncAttributeMaxDynamicSharedMemorySize, smem2);

    dim3 grid(SEQ / QT, BH);
    qk_kernel<<<grid, 256, smem1>>>(q, k, scale);
    pv_kernel<<<grid, 256, smem2>>>(v, out);
}

// round 17
// speedup vs baseline: 2.1533x; 2.1533x over previous
#include <cuda_runtime.h>
#include <cuda_bf16.h>
#include <cstdint>

// B=4,H=8,N=2048,D=64 fp32.  out = softmax(l * softmax(2l)) @ V,  l = qk^T*scale
#define BH   32
#define SEQ  2048
#define HD   64
#define MT   128           // q rows per CTA (8 warps x m16)
#define KT   128           // keys per tile (2 halves of 64)
#define NK   (SEQ / KT)    // 16
#define SKH  72            // smem row stride in halves: 144B rows -> 16B aligned + ldmatrix conflict-free
#define TILE_B (128 * SKH * 2)   // 18432 bytes per [128 x 64] bf16 tile

// bf16 hi/lo splits (~50MB) + softmax-1 row sums
__device__ __align__(16) __nv_bfloat16 gQh[(size_t)BH * SEQ * HD];
__device__ __align__(16) __nv_bfloat16 gQl[(size_t)BH * SEQ * HD];
__device__ __align__(16) __nv_bfloat16 gKh[(size_t)BH * SEQ * HD];
__device__ __align__(16) __nv_bfloat16 gKl[(size_t)BH * SEQ * HD];
__device__ __align__(16) __nv_bfloat16 gVh[(size_t)BH * SEQ * HD];
__device__ __align__(16) __nv_bfloat16 gVl[(size_t)BH * SEQ * HD];
__device__ float g_sum1[BH * SEQ];

// ---------------- helpers ----------------
__device__ __forceinline__ uint32_t smem_u32(const void* p) {
    uint32_t a;
    asm("{ .reg .u64 t; cvta.to.shared.u64 t, %1; cvt.u32.u64 %0, t; }" : "=r"(a) : "l"(p));
    return a;
}
__device__ __forceinline__ void ldsm4(uint32_t r[4], uint32_t addr) {
    asm volatile("ldmatrix.sync.aligned.m8n8.x4.shared.b16 {%0,%1,%2,%3}, [%4];"
                 : "=r"(r[0]), "=r"(r[1]), "=r"(r[2]), "=r"(r[3]) : "r"(addr));
}
__device__ __forceinline__ void ldsm4t(uint32_t r[4], uint32_t addr) {
    asm volatile("ldmatrix.sync.aligned.m8n8.x4.trans.shared.b16 {%0,%1,%2,%3}, [%4];"
                 : "=r"(r[0]), "=r"(r[1]), "=r"(r[2]), "=r"(r[3]) : "r"(addr));
}
// D += A(m16k16 bf16) * B(k16n8 bf16), fp32 accumulate
__device__ __forceinline__ void mma(float c[4], const uint32_t a[4], uint32_t b0, uint32_t b1) {
    asm volatile(
        "mma.sync.aligned.m16n8k16.row.col.f32.bf16.bf16.f32 "
        "{%0,%1,%2,%3}, {%4,%5,%6,%7}, {%8,%9}, {%0,%1,%2,%3};"
        : "+f"(c[0]), "+f"(c[1]), "+f"(c[2]), "+f"(c[3])
        : "r"(a[0]), "r"(a[1]), "r"(a[2]), "r"(a[3]), "r"(b0), "r"(b1));
}
// x4 ldmatrix lane-address byte offset: matrices (r0-7,c0) (r8-15,c0) (r0-7,c8) (r8-15,c8)
__device__ __forceinline__ uint32_t ldsm_off(int base_row, int lane, int base_colh) {
    int r = base_row + (lane & 7) + ((lane >> 3) & 1) * 8;
    int c = base_colh + (lane >> 4) * 8;
    return (uint32_t)(r * SKH + c) * 2;
}
__device__ __forceinline__ uint32_t pack_bf16x2(float a, float b) {
    __nv_bfloat162 t = __halves2bfloat162(__float2bfloat16(a), __float2bfloat16(b));
    return *reinterpret_cast<uint32_t*>(&t);
}
// gmem [128 x 64] bf16 -> smem stride-SKH tile; 1024 uint4, 256 thr = 4 each
__device__ __forceinline__ void load_tile(char* dst, const __nv_bfloat16* g, int tid) {
    const uint4* src = reinterpret_cast<const uint4*>(g);
    #pragma unroll
    for (int m = 0; m < 4; m++) {
        int idx = tid + 256 * m;
        int r = idx >> 3, c = idx & 7;                 // row, 16B-chunk
        *reinterpret_cast<uint4*>(dst + r * (SKH * 2) + c * 16) = src[idx];
    }
}

// ---------------- prep: fp32 -> bf16 hi/lo ----------------
__global__ void __launch_bounds__(256) prep_kernel(
    const float* __restrict__ q, const float* __restrict__ k, const float* __restrict__ v)
{
    size_t i = (size_t)blockIdx.x * 256 + threadIdx.x;
    const float4 a = reinterpret_cast<const float4*>(q)[i];
    const float4 b = reinterpret_cast<const float4*>(k)[i];
    const float4 c = reinterpret_cast<const float4*>(v)[i];
    #define SPLIT4(src, H, L) do {                                                   \
        float hx = __bfloat162float(__float2bfloat16(src.x));                        \
        float hy = __bfloat162float(__float2bfloat16(src.y));                        \
        float hz = __bfloat162float(__float2bfloat16(src.z));                        \
        float hw = __bfloat162float(__float2bfloat16(src.w));                        \
        reinterpret_cast<uint32_t*>(H)[2*i]   = pack_bf16x2(src.x, src.y);           \
        reinterpret_cast<uint32_t*>(H)[2*i+1] = pack_bf16x2(src.z, src.w);           \
        reinterpret_cast<uint32_t*>(L)[2*i]   = pack_bf16x2(src.x - hx, src.y - hy); \
        reinterpret_cast<uint32_t*>(L)[2*i+1] = pack_bf16x2(src.z - hz, src.w - hw); \
    } while (0)
    SPLIT4(a, gQh, gQl); SPLIT4(b, gKh, gKl); SPLIT4(c, gVh, gVl);
    #undef SPLIT4
}

// QK 3-term mma for one 64-key half into c[8][4].
// qa/ql: Q A-frags [kc][4]. KHp/KLp: smem byte bases of K hi/lo tiles.
__device__ __forceinline__ void qk_half(
    float c[8][4], const uint32_t qa[4][4], const uint32_t ql[4][4],
    uint32_t KHp, uint32_t KLp, int h, int lane)
{
    #pragma unroll
    for (int kc = 0; kc < 4; kc++) {
        #pragma unroll
        for (int pr = 0; pr < 4; pr++) {
            uint32_t bh4[4], bl4[4];
            uint32_t off = ldsm_off(64 * h + 16 * pr, lane, kc * 16);
            ldsm4(bh4, KHp + off);
            ldsm4(bl4, KLp + off);
            // x4 on K[n][k]: r0=b0(n 0-7), r1=b0(n 8-15), r2=b1(n 0-7), r3=b1(n 8-15)
            mma(c[2*pr],   qa[kc], bh4[0], bh4[2]);
            mma(c[2*pr+1], qa[kc], bh4[1], bh4[3]);
            mma(c[2*pr],   qa[kc], bl4[0], bl4[2]);
            mma(c[2*pr+1], qa[kc], bl4[1], bl4[3]);
            mma(c[2*pr],   ql[kc], bh4[0], bh4[2]);
            mma(c[2*pr+1], ql[kc], bh4[1], bh4[3]);
        }
    }
}

// ---------------- kernel 1: sum1 ----------------
__global__ void __launch_bounds__(256, 2) k1_sum1(const float* __restrict__ scale_p)
{
    extern __shared__ char sm[];
    const uint32_t sb = smem_u32(sm);
    const int tid = threadIdx.x, w = tid >> 5, lane = tid & 31;
    const int g = lane >> 2, t = lane & 3;
    const int bh = blockIdx.y, q0 = blockIdx.x * MT;
    const float scale = *scale_p;

    char* QH = sm; char* QL = sm + TILE_B; char* KH = sm + 2*TILE_B; char* KL = sm + 3*TILE_B;
    const size_t qoff = ((size_t)bh * SEQ + q0) * HD;
    load_tile(QH, gQh + qoff, tid);
    load_tile(QL, gQl + qoff, tid);
    __syncthreads();

    uint32_t qa[4][4], ql[4][4];
    #pragma unroll
    for (int kc = 0; kc < 4; kc++) {
        uint32_t off = ldsm_off(16 * w, lane, kc * 16);
        ldsm4(qa[kc], sb + off);
        ldsm4(ql[kc], sb + TILE_B + off);
    }

    float s1a = 0.f, s1b = 0.f;
    for (int kt = 0; kt < NK; kt++) {
        __syncthreads();
        const size_t koff = ((size_t)bh * SEQ + kt * KT) * HD;
        load_tile(KH, gKh + koff, tid);
        load_tile(KL, gKl + koff, tid);
        __syncthreads();
        #pragma unroll
        for (int h = 0; h < 2; h++) {
            float c[8][4];
            #pragma unroll
            for (int n = 0; n < 8; n++)
                { c[n][0]=0.f; c[n][1]=0.f; c[n][2]=0.f; c[n][3]=0.f; }
            qk_half(c, qa, ql, sb + 2*TILE_B, sb + 3*TILE_B, h, lane);
            #pragma unroll
            for (int n = 0; n < 8; n++) {
                s1a += __expf(2.f * (c[n][0] * scale));
                s1a += __expf(2.f * (c[n][1] * scale));
                s1b += __expf(2.f * (c[n][2] * scale));
                s1b += __expf(2.f * (c[n][3] * scale));
            }
        }
    }
    s1a += __shfl_xor_sync(0xffffffffu, s1a, 1);
    s1a += __shfl_xor_sync(0xffffffffu, s1a, 2);
    s1b += __shfl_xor_sync(0xffffffffu, s1b, 1);
    s1b += __shfl_xor_sync(0xffffffffu, s1b, 2);
    if (t == 0) {
        g_sum1[bh * SEQ + q0 + 16 * w + g]     = s1a;
        g_sum1[bh * SEQ + q0 + 16 * w + g + 8] = s1b;
    }
}

// ---------------- kernel 2: recompute QK, P = exp(l*mask), O = P V / sum2 ----------------
__global__ void __launch_bounds__(256, 1) k2_pv(
    const float* __restrict__ scale_p, float* __restrict__ out)
{
    extern __shared__ char sm[];
    const uint32_t sb = smem_u32(sm);
    const int tid = threadIdx.x, w = tid >> 5, lane = tid & 31;
    const int g = lane >> 2, t = lane & 3;
    const int bh = blockIdx.y, q0 = blockIdx.x * MT;
    const float scale = *scale_p;

    char* QH = sm;             char* QL = sm + TILE_B;
    char* KH = sm + 2*TILE_B;  char* KL = sm + 3*TILE_B;
    char* VH = sm + 4*TILE_B;  char* VL = sm + 5*TILE_B;

    const size_t qoff = ((size_t)bh * SEQ + q0) * HD;
    load_tile(QH, gQh + qoff, tid);
    load_tile(QL, gQl + qoff, tid);
    __syncthreads();

    uint32_t qa[4][4], ql[4][4];
    #pragma unroll
    for (int kc = 0; kc < 4; kc++) {
        uint32_t off = ldsm_off(16 * w, lane, kc * 16);
        ldsm4(qa[kc], sb + off);
        ldsm4(ql[kc], sb + TILE_B + off);
    }

    const float inv1a = 1.f / g_sum1[bh * SEQ + q0 + 16 * w + g];
    const float inv1b = 1.f / g_sum1[bh * SEQ + q0 + 16 * w + g + 8];
    float s2a = 0.f, s2b = 0.f;
    float o[8][4];
    #pragma unroll
    for (int d = 0; d < 8; d++) { o[d][0]=0.f; o[d][1]=0.f; o[d][2]=0.f; o[d][3]=0.f; }

    for (int kt = 0; kt < NK; kt++) {
        __syncthreads();
        const size_t koff = ((size_t)bh * SEQ + kt * KT) * HD;
        load_tile(KH, gKh + koff, tid);
        load_tile(KL, gKl + koff, tid);
        load_tile(VH, gVh + koff, tid);
        load_tile(VL, gVl + koff, tid);
        __syncthreads();

        #pragma unroll
        for (int h = 0; h < 2; h++) {
            float c[8][4];
            #pragma unroll
            for (int n = 0; n < 8; n++)
                { c[n][0]=0.f; c[n][1]=0.f; c[n][2]=0.f; c[n][3]=0.f; }
            qk_half(c, qa, ql, sb + 2*TILE_B, sb + 3*TILE_B, h, lane);

            // epilogue: p = exp(l * exp(2l)*inv1); build P A-frags (FA2 C->A conversion)
            uint32_t pah[4][4], pal[4][4];   // [pc][reg]
            #pragma unroll
            for (int n = 0; n < 8; n++) {
                float p[4];
                #pragma unroll
                for (int e = 0; e < 4; e++) {
                    float l   = c[n][e] * scale;
                    float msk = __expf(2.f * l) * ((e < 2) ? inv1a : inv1b);
                    p[e] = __expf(l * msk);
                }
                s2a += p[0] + p[1];
                s2b += p[2] + p[3];
                float h0 = __bfloat162float(__float2bfloat16(p[0]));
                float h1 = __bfloat162float(__float2bfloat16(p[1]));
                float h2 = __bfloat162float(__float2bfloat16(p[2]));
                float h3 = __bfloat162float(__float2bfloat16(p[3]));
                int pc = n >> 1, rb = (n & 1) * 2;
                pah[pc][rb]     = pack_bf16x2(p[0], p[1]);          // (g,   k 2t,2t+1)
                pah[pc][rb + 1] = pack_bf16x2(p[2], p[3]);          // (g+8, k 2t,2t+1)
                pal[pc][rb]     = pack_bf16x2(p[0] - h0, p[1] - h1);
                pal[pc][rb + 1] = pack_bf16x2(p[2] - h2, p[3] - h3);
            }

            // PV: O += Ph*Vh + Ph*Vl + Pl*Vh  (V via ldmatrix.x4.trans)
            #pragma unroll
            for (int pc = 0; pc < 4; pc++) {
                #pragma unroll
                for (int dp = 0; dp < 4; dp++) {
                    uint32_t vh4[4], vl4[4];
                    uint32_t off = ldsm_off(64 * h + 16 * pc, lane, dp * 16);
                    ldsm4t(vh4, sb + 4*TILE_B + off);
                    ldsm4t(vl4, sb + 5*TILE_B + off);
                    // trans x4 on V[k][d]: r0,r1 = b0,b1 (d 0-7 of chunk); r2,r3 = d 8-15
                    mma(o[2*dp],   pah[pc], vh4[0], vh4[1]);
                    mma(o[2*dp+1], pah[pc], vh4[2], vh4[3]);
                    mma(o[2*dp],   pah[pc], vl4[0], vl4[1]);
                    mma(o[2*dp+1], pah[pc], vl4[2], vl4[3]);
                    mma(o[2*dp],   pal[pc], vh4[0], vh4[1]);
                    mma(o[2*dp+1], pal[pc], vh4[2], vh4[3]);
                }
            }
        }
    }

    // normalize + store
    s2a += __shfl_xor_sync(0xffffffffu, s2a, 1);
    s2a += __shfl_xor_sync(0xffffffffu, s2a, 2);
    s2b += __shfl_xor_sync(0xffffffffu, s2b, 1);
    s2b += __shfl_xor_sync(0xffffffffu, s2b, 2);
    const float inv2a = 1.f / s2a, inv2b = 1.f / s2b;

    const int r0 = q0 + 16 * w + g;
    float* ob = out + ((size_t)bh * SEQ) * HD;
    #pragma unroll
    for (int d = 0; d < 8; d++) {
        int col = 8 * d + 2 * t;
        *reinterpret_cast<float2*>(ob + (size_t)r0 * HD + col) =
            make_float2(o[d][0] * inv2a, o[d][1] * inv2a);
        *reinterpret_cast<float2*>(ob + (size_t)(r0 + 8) * HD + col) =
            make_float2(o[d][2] * inv2b, o[d][3] * inv2b);
    }
}

// ---------------- launch ----------------
extern "C" void kernel_launch(void* const* d_in, const int* in_sizes, int n_in,
                              void* d_out, int out_size)
{
    const float* q     = (const float*)d_in[0];
    const float* k     = (const float*)d_in[1];
    const float* v     = (const float*)d_in[2];
    const float* scale = (const float*)d_in[3];
    float* out = (float*)d_out;

    const int smem1 = 4 * TILE_B;   // 73728
    const int smem2 = 6 * TILE_B;   // 110592
    cudaFuncSetAttribute(k1_sum1, cudaFuncAttributeMaxDynamicSharedMemorySize, smem1);
    cudaFuncSetAttribute(k2_pv,   cudaFuncAttributeMaxDynamicSharedMemorySize, smem2);

    prep_kernel<<<(BH * SEQ * HD / 4) / 256, 256>>>(q, k, v);
    dim3 grid(SEQ / MT, BH);
    k1_sum1<<<grid, 256, smem1>>>(scale);
    k2_pv<<<grid, 256, smem2>>>(scale, out);
}